// round 5
// baseline (speedup 1.0000x reference)
#include <cuda_runtime.h>

#define NN 100000
#define EE 1600000
#define KHOP 50
#define SCAN_BS 1024
#define NBLK_SCAN ((NN + SCAN_BS - 1) / SCAN_BS)

// ---------------- device scratch (static, no allocation) ----------------
__device__ float g_deg[NN];
__device__ float g_dis[NN];
__device__ int   g_cnt[NN];
__device__ int   g_off[NN + 1];
__device__ int   g_cur[NN];
__device__ int   g_bsum[NBLK_SCAN];
__device__ int   g_boff[NBLK_SCAN];
__device__ int2  g_csc[EE + 8];    // {src, bitcast(norm)}; +8 zero pad for unroll
__device__ float g_ha[NN * 32];
__device__ float g_hb[NN * 32];
__device__ float g_acc1[NN * 32];
__device__ float g_acc2[NN * 32];
__device__ float g_x3[NN * 32];
__device__ float g_z4[(KHOP + 1) * NN];
__device__ float g_t4a[NN];
__device__ float g_t4b[NN];

// ---------------- setup kernels ----------------
__global__ void k_zero() {
    int i = blockIdx.x * blockDim.x + threadIdx.x;
    if (i < NN) { g_deg[i] = 0.f; g_cnt[i] = 0; }
}

__global__ void k_degcnt(const int* __restrict__ ei, const float* __restrict__ ew) {
    int e = blockIdx.x * blockDim.x + threadIdx.x;
    if (e < EE) {
        int c = ei[EE + e];
        atomicAdd(&g_deg[c], ew[e]);
        atomicAdd(&g_cnt[c], 1);
    }
}

__global__ void k_dis() {
    int i = blockIdx.x * blockDim.x + threadIdx.x;
    if (i < NN) {
        float d = g_deg[i];
        g_dis[i] = (d > 0.f) ? (1.0f / sqrtf(d)) : 0.f;
    }
}

__global__ void k_bsum() {
    __shared__ int ws[32];
    int tid = threadIdx.x, lane = tid & 31, wid = tid >> 5;
    int i = blockIdx.x * SCAN_BS + tid;
    int v = (i < NN) ? g_cnt[i] : 0;
    #pragma unroll
    for (int d = 16; d >= 1; d >>= 1) v += __shfl_down_sync(0xffffffffu, v, d);
    if (lane == 0) ws[wid] = v;
    __syncthreads();
    if (wid == 0) {
        int y = ws[lane];
        #pragma unroll
        for (int d = 16; d >= 1; d >>= 1) y += __shfl_down_sync(0xffffffffu, y, d);
        if (lane == 0) g_bsum[blockIdx.x] = y;
    }
}

__global__ void k_bscan() {
    __shared__ int ws[4];
    int tid = threadIdx.x, lane = tid & 31, wid = tid >> 5;
    int v = (tid < NBLK_SCAN) ? g_bsum[tid] : 0;
    int x = v;
    #pragma unroll
    for (int d = 1; d < 32; d <<= 1) {
        int t = __shfl_up_sync(0xffffffffu, x, d);
        if (lane >= d) x += t;
    }
    if (lane == 31) ws[wid] = x;
    __syncthreads();
    int base = 0;
    for (int w = 0; w < wid; w++) base += ws[w];
    if (tid < NBLK_SCAN) g_boff[tid] = base + x - v;
}

__global__ void k_scan2() {
    __shared__ int ws[32];
    int tid = threadIdx.x, lane = tid & 31, wid = tid >> 5;
    int i = blockIdx.x * SCAN_BS + tid;
    int v = (i < NN) ? g_cnt[i] : 0;
    int x = v;
    #pragma unroll
    for (int d = 1; d < 32; d <<= 1) {
        int t = __shfl_up_sync(0xffffffffu, x, d);
        if (lane >= d) x += t;
    }
    if (lane == 31) ws[wid] = x;
    __syncthreads();
    if (wid == 0) {
        int y = ws[lane];
        #pragma unroll
        for (int d = 1; d < 32; d <<= 1) {
            int t = __shfl_up_sync(0xffffffffu, y, d);
            if (lane >= d) y += t;
        }
        ws[lane] = y;
    }
    __syncthreads();
    int excl = g_boff[blockIdx.x] + (wid ? ws[wid - 1] : 0) + x - v;
    if (i < NN) {
        g_off[i] = excl;
        g_cur[i] = excl;
        if (i == NN - 1) g_off[NN] = excl + v;
    }
}

__global__ void k_scatter(const int* __restrict__ ei, const float* __restrict__ ew) {
    int e = blockIdx.x * blockDim.x + threadIdx.x;
    if (e < EE) {
        int r = ei[e], c = ei[EE + e];
        float nrm = g_dis[r] * ew[e] * g_dis[c];
        int p = atomicAdd(&g_cur[c], 1);
        g_csc[p] = make_int2(r, __float_as_int(nrm));
    }
}

// ---------------- layer 1 (forward, fin=2, fout=15, acc1) ----------------
__global__ void k_init1(const float* __restrict__ c, const int* __restrict__ ip,
                        const float* __restrict__ W, const float* __restrict__ b) {
    __shared__ float sW[30];
    __shared__ float sb[15];
    if (threadIdx.x < 30) sW[threadIdx.x] = W[threadIdx.x];
    if (threadIdx.x < 15) sb[threadIdx.x] = b[threadIdx.x];
    __syncthreads();
    int n = blockIdx.x * blockDim.x + threadIdx.x;
    if (n >= NN) return;
    int iv = ip[0];
    float cv = (n == iv) ? 1.f : 0.f;
    float cc = c[n];
    ((float2*)g_ha)[n] = make_float2(cv, cc);
    float o[16];
    #pragma unroll
    for (int j = 0; j < 15; j++) o[j] = sb[j] + cv * sW[j] + cc * sW[15 + j];
    o[15] = 0.f;
    float4* ap = (float4*)(g_acc1 + n * 16);
    ap[0] = *(float4*)(o + 0); ap[1] = *(float4*)(o + 4);
    ap[2] = *(float4*)(o + 8); ap[3] = *(float4*)(o + 12);
}

// 4 lanes/node, each lane owns edges t+l, t+l+4; group-masked shfl reduce.
__global__ void k_spmm1(int pp, const float* __restrict__ Wk) {
    __shared__ float sWx[16];
    __shared__ float sWy[16];
    int tid = threadIdx.x;
    if (tid < 16) {
        sWx[tid] = (tid < 15) ? Wk[tid] : 0.f;
        sWy[tid] = (tid < 15) ? Wk[15 + tid] : 0.f;
    }
    __syncthreads();
    int g = tid >> 2, l = tid & 3;
    int n = blockIdx.x * 64 + g;
    bool valid = (n < NN);
    unsigned gmask = 0xFu << ((tid & 31) & ~3);
    const float2* hc = (const float2*)(pp ? g_hb : g_ha);
    float2* hn = (float2*)(pp ? g_ha : g_hb);
    int s = 0, e = 0;
    if (valid) { s = g_off[n]; e = g_off[n + 1]; }
    float ax = 0.f, ay = 0.f;
    for (int t = s; t < e; t += 8) {
        int i0 = t + l, i1 = t + l + 4;
        int2 a0 = g_csc[i0];
        int2 a1 = g_csc[i1];
        if (i0 >= e) a0.y = 0;
        if (i1 >= e) a1.y = 0;
        float2 v0 = hc[a0.x];
        float2 v1 = hc[a1.x];
        float w0 = __int_as_float(a0.y), w1 = __int_as_float(a1.y);
        ax = fmaf(w0, v0.x, ax); ay = fmaf(w0, v0.y, ay);
        ax = fmaf(w1, v1.x, ax); ay = fmaf(w1, v1.y, ay);
    }
    ax += __shfl_xor_sync(gmask, ax, 1, 4);
    ax += __shfl_xor_sync(gmask, ax, 2, 4);
    ay += __shfl_xor_sync(gmask, ay, 1, 4);
    ay += __shfl_xor_sync(gmask, ay, 2, 4);
    if (!valid) return;
    if (l == 0) hn[n] = make_float2(ax, ay);
    // acc1 quarter update: lane l handles floats 4l..4l+3
    float4* ap = (float4*)(g_acc1 + n * 16);
    float4 o = ap[l];
    int j0 = l * 4;
    o.x += ax * sWx[j0 + 0] + ay * sWy[j0 + 0];
    o.y += ax * sWx[j0 + 1] + ay * sWy[j0 + 1];
    o.z += ax * sWx[j0 + 2] + ay * sWy[j0 + 2];
    o.w += ax * sWx[j0 + 3] + ay * sWy[j0 + 3];
    ap[l] = o;
}

// ---------------- layer 2 (forward, 4 lanes/node, rows = 16 floats) --------
__global__ void k_spmm2(int pp, const float* __restrict__ Wk) {
    constexpr int NPB = 64, FIN = 15, FOUT = 30, FOUTP = 32;
    __shared__ float sm[NPB][16];
    __shared__ float sW[FIN * FOUT];
    for (int idx = threadIdx.x; idx < FIN * FOUT; idx += 256) sW[idx] = Wk[idx];
    const float4* h4 = (const float4*)(pp ? g_hb : g_ha);
    float4* hn = (float4*)(pp ? g_ha : g_hb);
    int g = threadIdx.x >> 2;
    int l = threadIdx.x & 3;
    int n = blockIdx.x * NPB + g;
    bool valid = (n < NN);
    unsigned gmask = 0xFu << ((threadIdx.x & 31) & ~3);
    int s = 0, e = 0;
    if (valid) { s = g_off[n]; e = g_off[n + 1]; }
    float4 acc = make_float4(0.f, 0.f, 0.f, 0.f);
    for (int t = s; t < e; t += 8) {
        int i0 = t + l, i1 = t + l + 4;
        int2 a0 = g_csc[i0];
        int2 a1 = g_csc[i1];
        if (i0 >= e) a0.y = 0;
        if (i1 >= e) a1.y = 0;
        int src[8]; int wbits[8];
        #pragma unroll
        for (int j = 0; j < 4; j++) {
            src[j]       = __shfl_sync(gmask, a0.x, j, 4);
            wbits[j]     = __shfl_sync(gmask, a0.y, j, 4);
            src[4 + j]   = __shfl_sync(gmask, a1.x, j, 4);
            wbits[4 + j] = __shfl_sync(gmask, a1.y, j, 4);
        }
        float4 v[8];
        #pragma unroll
        for (int j = 0; j < 8; j++) v[j] = h4[src[j] * 4 + l];
        #pragma unroll
        for (int j = 0; j < 8; j++) {
            float w = __int_as_float(wbits[j]);
            acc.x = fmaf(w, v[j].x, acc.x); acc.y = fmaf(w, v[j].y, acc.y);
            acc.z = fmaf(w, v[j].z, acc.z); acc.w = fmaf(w, v[j].w, acc.w);
        }
    }
    if (valid) hn[n * 4 + l] = acc;
    *(float4*)&sm[g][l * 4] = acc;
    __syncthreads();
    for (int idx = threadIdx.x; idx < NPB * FOUT; idx += 256) {
        int nl = idx / FOUT, j = idx - nl * FOUT;
        int n2 = blockIdx.x * NPB + nl;
        if (n2 < NN) {
            float sum = 0.f;
            #pragma unroll
            for (int f = 0; f < FIN; f++) sum = fmaf(sm[nl][f], sW[f * FOUT + j], sum);
            g_acc2[n2 * FOUTP + j] += sum;
        }
    }
}

// ---------------- transition 1->2 ----------------
__global__ void k_trans12(const float* __restrict__ W, const float* __restrict__ b) {
    __shared__ float sW[450];
    __shared__ float sb[30];
    for (int idx = threadIdx.x; idx < 450; idx += 256) sW[idx] = W[idx];
    if (threadIdx.x < 30) sb[threadIdx.x] = b[threadIdx.x];
    __syncthreads();
    int n = blockIdx.x * blockDim.x + threadIdx.x;
    if (n >= NN) return;
    float v[16];
    const float4* ap = (const float4*)(g_acc1 + n * 16);
    *(float4*)(v + 0) = ap[0]; *(float4*)(v + 4) = ap[1];
    *(float4*)(v + 8) = ap[2]; *(float4*)(v + 12) = ap[3];
    #pragma unroll
    for (int f = 0; f < 15; f++) v[f] = fmaxf(v[f], 0.f);
    v[15] = 0.f;
    float4* hp = (float4*)(g_ha + n * 16);
    hp[0] = *(float4*)(v + 0); hp[1] = *(float4*)(v + 4);
    hp[2] = *(float4*)(v + 8); hp[3] = *(float4*)(v + 12);
    float o[32];
    #pragma unroll
    for (int j = 0; j < 30; j++) o[j] = sb[j];
    o[30] = 0.f; o[31] = 0.f;
    #pragma unroll
    for (int f = 0; f < 15; f++) {
        float vf = v[f];
        #pragma unroll
        for (int j = 0; j < 30; j++) o[j] = fmaf(vf, sW[f * 30 + j], o[j]);
    }
    float4* op = (float4*)(g_acc2 + n * 32);
    #pragma unroll
    for (int q = 0; q < 8; q++) op[q] = *(float4*)(o + 4 * q);
}

// ---- transition 2->3 (Horner init): x3 = relu(acc2); t_K = x3 W3[K] --------
__global__ void k_trans23(const float* __restrict__ WK) {
    __shared__ float sW[450];
    for (int idx = threadIdx.x; idx < 450; idx += 256) sW[idx] = WK[idx];
    __syncthreads();
    int n = blockIdx.x * blockDim.x + threadIdx.x;
    if (n >= NN) return;
    float v[32];
    const float4* ap = (const float4*)(g_acc2 + n * 32);
    #pragma unroll
    for (int q = 0; q < 8; q++) *(float4*)(v + 4 * q) = ap[q];
    #pragma unroll
    for (int f = 0; f < 30; f++) v[f] = fmaxf(v[f], 0.f);
    v[30] = 0.f; v[31] = 0.f;
    float4* xp = (float4*)(g_x3 + n * 32);
    #pragma unroll
    for (int q = 0; q < 8; q++) xp[q] = *(float4*)(v + 4 * q);
    float o[16];
    #pragma unroll
    for (int j = 0; j < 16; j++) o[j] = 0.f;
    #pragma unroll
    for (int f = 0; f < 30; f++) {
        float vf = v[f];
        #pragma unroll
        for (int j = 0; j < 15; j++) o[j] = fmaf(vf, sW[f * 15 + j], o[j]);
    }
    float4* tp = (float4*)(g_ha + n * 16);
    #pragma unroll
    for (int q = 0; q < 4; q++) tp[q] = *(float4*)(o + 4 * q);
}

// ------- layer 3 Horner hop: t_new = x3 W3_k [+ b3 if last] + A t_old -------
__global__ void k_hop3(int pp, const float* __restrict__ Wk, int addb,
                       const float* __restrict__ b) {
    __shared__ float sW[32 * 16];   // rows 30,31 and col 15 zero-padded
    __shared__ float sb[16];
    int tid = threadIdx.x;
    for (int idx = tid; idx < 512; idx += 256) {
        int f = idx >> 4, j = idx & 15;
        sW[idx] = (f < 30 && j < 15) ? Wk[f * 15 + j] : 0.f;
    }
    if (tid < 16) sb[tid] = (addb && tid < 15) ? b[tid] : 0.f;
    __syncthreads();
    int g = tid >> 2, l = tid & 3;
    int n = blockIdx.x * 64 + g;
    bool valid = (n < NN);
    unsigned gmask = 0xFu << ((tid & 31) & ~3);
    const float4* t_old = (const float4*)(pp ? g_hb : g_ha);
    float4* t_new = (float4*)(pp ? g_ha : g_hb);
    int s = 0, e = 0;
    if (valid) { s = g_off[n]; e = g_off[n + 1]; }
    float4 acc = make_float4(0.f, 0.f, 0.f, 0.f);
    for (int t = s; t < e; t += 8) {
        int i0 = t + l, i1 = t + l + 4;
        int2 a0 = g_csc[i0];
        int2 a1 = g_csc[i1];
        if (i0 >= e) a0.y = 0;
        if (i1 >= e) a1.y = 0;
        int src[8]; int wbits[8];
        #pragma unroll
        for (int j = 0; j < 4; j++) {
            src[j]       = __shfl_sync(gmask, a0.x, j, 4);
            wbits[j]     = __shfl_sync(gmask, a0.y, j, 4);
            src[4 + j]   = __shfl_sync(gmask, a1.x, j, 4);
            wbits[4 + j] = __shfl_sync(gmask, a1.y, j, 4);
        }
        float4 v[8];
        #pragma unroll
        for (int j = 0; j < 8; j++) v[j] = t_old[src[j] * 4 + l];
        #pragma unroll
        for (int j = 0; j < 8; j++) {
            float w = __int_as_float(wbits[j]);
            acc.x = fmaf(w, v[j].x, acc.x); acc.y = fmaf(w, v[j].y, acc.y);
            acc.z = fmaf(w, v[j].z, acc.z); acc.w = fmaf(w, v[j].w, acc.w);
        }
    }
    if (!valid) return;
    // z-term: x3[n] . W3_k[:, 4l .. 4l+3]
    int j0 = l * 4;
    float zx = sb[j0], zy = sb[j0 + 1], zz = sb[j0 + 2], zw = sb[j0 + 3];
    const float4* xr = (const float4*)(g_x3 + n * 32);
    #pragma unroll
    for (int q = 0; q < 8; q++) {
        float4 xq = xr[q];
        const float* w0 = &sW[(4 * q) * 16 + j0];
        const float* w1 = &sW[(4 * q + 1) * 16 + j0];
        const float* w2 = &sW[(4 * q + 2) * 16 + j0];
        const float* w3 = &sW[(4 * q + 3) * 16 + j0];
        zx = fmaf(xq.x, w0[0], zx); zy = fmaf(xq.x, w0[1], zy);
        zz = fmaf(xq.x, w0[2], zz); zw = fmaf(xq.x, w0[3], zw);
        zx = fmaf(xq.y, w1[0], zx); zy = fmaf(xq.y, w1[1], zy);
        zz = fmaf(xq.y, w1[2], zz); zw = fmaf(xq.y, w1[3], zw);
        zx = fmaf(xq.z, w2[0], zx); zy = fmaf(xq.z, w2[1], zy);
        zz = fmaf(xq.z, w2[2], zz); zw = fmaf(xq.z, w2[3], zw);
        zx = fmaf(xq.w, w3[0], zx); zy = fmaf(xq.w, w3[1], zy);
        zz = fmaf(xq.w, w3[2], zz); zw = fmaf(xq.w, w3[3], zw);
    }
    acc.x += zx; acc.y += zy; acc.z += zz; acc.w += zw;
    t_new[n * 4 + l] = acc;
}

// ---- transition 3->4: x4 = relu(t3); z4[k][n] = x4 . W4_k (+b4 at k=0) -----
__global__ void k_z4(const float* __restrict__ W4, const float* __restrict__ b4) {
    __shared__ float sW[(KHOP + 1) * 15];
    __shared__ float sb0;
    for (int idx = threadIdx.x; idx < (KHOP + 1) * 15; idx += 256) sW[idx] = W4[idx];
    if (threadIdx.x == 0) sb0 = b4[0];
    __syncthreads();
    int n = blockIdx.x * blockDim.x + threadIdx.x;
    if (n >= NN) return;
    float v[16];
    const float4* tp = (const float4*)(g_ha + n * 16);  // 50 hops -> final t3 in g_ha
    *(float4*)(v + 0) = tp[0]; *(float4*)(v + 4) = tp[1];
    *(float4*)(v + 8) = tp[2]; *(float4*)(v + 12) = tp[3];
    #pragma unroll
    for (int f = 0; f < 15; f++) v[f] = fmaxf(v[f], 0.f);
    for (int k = 0; k <= KHOP; k++) {
        float z = (k == 0) ? sb0 : 0.f;
        #pragma unroll
        for (int f = 0; f < 15; f++) z = fmaf(v[f], sW[k * 15 + f], z);
        g_z4[k * NN + n] = z;
    }
}

// ------------- layer 4 Horner hop (width 1, 4 lanes/node) -------------------
// mode: 0 -> told = g_z4[K], 1 -> told = g_t4a, 2 -> told = g_t4b
// fin: if nonzero, write relu to out instead of tnew
__global__ void k_hop4(int mode, int wout, int kidx, int fin, float* __restrict__ out) {
    int tid = threadIdx.x;
    int g = tid >> 2, l = tid & 3;
    int n = blockIdx.x * 64 + g;
    bool valid = (n < NN);
    unsigned gmask = 0xFu << ((tid & 31) & ~3);
    const float* told = (mode == 0) ? (g_z4 + KHOP * NN) : (mode == 1 ? g_t4a : g_t4b);
    float* tnew = wout ? g_t4b : g_t4a;
    int s = 0, e = 0;
    if (valid) { s = g_off[n]; e = g_off[n + 1]; }
    float sum = 0.f;
    for (int t = s; t < e; t += 8) {
        int i0 = t + l, i1 = t + l + 4;
        int2 a0 = g_csc[i0];
        int2 a1 = g_csc[i1];
        if (i0 >= e) a0.y = 0;
        if (i1 >= e) a1.y = 0;
        float v0 = __ldg(told + a0.x);
        float v1 = __ldg(told + a1.x);
        sum = fmaf(__int_as_float(a0.y), v0, sum);
        sum = fmaf(__int_as_float(a1.y), v1, sum);
    }
    sum += __shfl_xor_sync(gmask, sum, 1, 4);
    sum += __shfl_xor_sync(gmask, sum, 2, 4);
    if (valid && l == 0) {
        float r = g_z4[kidx * NN + n] + sum;
        if (fin) out[n] = fmaxf(r, 0.f);
        else tnew[n] = r;
    }
}

// ---------------- host launch ----------------
static inline int div_up(int a, int b) { return (a + b - 1) / b; }

extern "C" void kernel_launch(void* const* d_in, const int* in_sizes, int n_in,
                              void* d_out, int out_size) {
    const int*   ei = (const int*)d_in[0];
    const float* ew = (const float*)d_in[1];
    const float* c  = (const float*)d_in[2];
    const int*   ip = (const int*)d_in[3];
    const float* W1 = (const float*)d_in[4];
    const float* b1 = (const float*)d_in[5];
    const float* W2 = (const float*)d_in[6];
    const float* b2 = (const float*)d_in[7];
    const float* W3 = (const float*)d_in[8];
    const float* b3 = (const float*)d_in[9];
    const float* W4 = (const float*)d_in[10];
    const float* b4 = (const float*)d_in[11];
    float* out = (float*)d_out;

    int nb = div_up(NN, 256);
    int eb = div_up(EE, 256);
    int hb = div_up(NN, 64);   // 4 lanes/node hop kernels

    // graph preprocessing
    k_zero<<<nb, 256>>>();
    k_degcnt<<<eb, 256>>>(ei, ew);
    k_dis<<<nb, 256>>>();
    k_bsum<<<NBLK_SCAN, SCAN_BS>>>();
    k_bscan<<<1, 128>>>();
    k_scan2<<<NBLK_SCAN, SCAN_BS>>>();
    k_scatter<<<eb, 256>>>(ei, ew);

    // layer 1: forward, acc1
    k_init1<<<nb, 256>>>(c, ip, W1, b1);
    int pp = 0;
    for (int k = 1; k <= KHOP; k++) {
        k_spmm1<<<hb, 256>>>(pp, W1 + k * 2 * 15);
        pp ^= 1;
    }

    // layer 2: forward, acc2
    k_trans12<<<nb, 256>>>(W2, b2);
    pp = 0;
    for (int k = 1; k <= KHOP; k++) {
        k_spmm2<<<hb, 256>>>(pp, W2 + k * 450);
        pp ^= 1;
    }

    // layer 3: Horner, width 16 (final t3 lands in g_ha after 50 hops)
    k_trans23<<<nb, 256>>>(W3 + KHOP * 450);
    pp = 0;
    for (int k = KHOP - 1; k >= 0; k--) {
        k_hop3<<<hb, 256>>>(pp, W3 + k * 450, (k == 0) ? 1 : 0, b3);
        pp ^= 1;
    }

    // layer 4: Horner, width 1 with precomputed z; final hop writes out
    k_z4<<<nb, 256>>>(W4, b4);
    int mode = 0, w = 0;
    for (int k = KHOP - 1; k >= 0; k--) {
        k_hop4<<<hb, 256>>>(mode, w, k, (k == 0) ? 1 : 0, out);
        mode = w ? 2 : 1;
        w ^= 1;
    }
}

// round 6
// speedup vs baseline: 1.1572x; 1.1572x over previous
#include <cuda_runtime.h>

#define NN 100000
#define EE 1600000
#define KHOP 50
#define SCAN_BS 1024
#define NBLK_SCAN ((NN + SCAN_BS - 1) / SCAN_BS)

// ---------------- device scratch (static, no allocation) ----------------
__device__ float g_deg[NN];
__device__ float g_dis[NN];
__device__ int   g_cnt[NN];
__device__ int   g_off[NN + 1];
__device__ int   g_cur[NN];
__device__ int   g_bsum[NBLK_SCAN];
__device__ int   g_boff[NBLK_SCAN];
__device__ int2  g_csc[EE + 8];                      // {src, bitcast(norm)}; zero pad
__device__ float g_h1[(KHOP + 1) * NN * 2];          // layer-1 hop history (2-wide)
__device__ float g_h2[(size_t)(KHOP + 1) * NN * 16]; // layer-2 hop history (16-wide)
__device__ float g_z3[(size_t)(KHOP + 1) * NN * 16]; // layer-3 z_k = x3 W3_k (16-wide)
__device__ float g_x3[NN * 32];
__device__ float g_ha[NN * 16];                      // layer-3 Horner ping
__device__ float g_hb[NN * 16];                      // layer-3 Horner pong
__device__ float g_z4[(KHOP + 1) * NN];
__device__ float g_t4a[NN];
__device__ float g_t4b[NN];

// ---------------- setup kernels ----------------
__global__ void k_zero() {
    int i = blockIdx.x * blockDim.x + threadIdx.x;
    if (i < NN) { g_deg[i] = 0.f; g_cnt[i] = 0; }
}

__global__ void k_degcnt(const int* __restrict__ ei, const float* __restrict__ ew) {
    int e = blockIdx.x * blockDim.x + threadIdx.x;
    if (e < EE) {
        int c = ei[EE + e];
        atomicAdd(&g_deg[c], ew[e]);
        atomicAdd(&g_cnt[c], 1);
    }
}

__global__ void k_dis() {
    int i = blockIdx.x * blockDim.x + threadIdx.x;
    if (i < NN) {
        float d = g_deg[i];
        g_dis[i] = (d > 0.f) ? (1.0f / sqrtf(d)) : 0.f;
    }
}

__global__ void k_bsum() {
    __shared__ int ws[32];
    int tid = threadIdx.x, lane = tid & 31, wid = tid >> 5;
    int i = blockIdx.x * SCAN_BS + tid;
    int v = (i < NN) ? g_cnt[i] : 0;
    #pragma unroll
    for (int d = 16; d >= 1; d >>= 1) v += __shfl_down_sync(0xffffffffu, v, d);
    if (lane == 0) ws[wid] = v;
    __syncthreads();
    if (wid == 0) {
        int y = ws[lane];
        #pragma unroll
        for (int d = 16; d >= 1; d >>= 1) y += __shfl_down_sync(0xffffffffu, y, d);
        if (lane == 0) g_bsum[blockIdx.x] = y;
    }
}

__global__ void k_bscan() {
    __shared__ int ws[4];
    int tid = threadIdx.x, lane = tid & 31, wid = tid >> 5;
    int v = (tid < NBLK_SCAN) ? g_bsum[tid] : 0;
    int x = v;
    #pragma unroll
    for (int d = 1; d < 32; d <<= 1) {
        int t = __shfl_up_sync(0xffffffffu, x, d);
        if (lane >= d) x += t;
    }
    if (lane == 31) ws[wid] = x;
    __syncthreads();
    int base = 0;
    for (int w = 0; w < wid; w++) base += ws[w];
    if (tid < NBLK_SCAN) g_boff[tid] = base + x - v;
}

__global__ void k_scan2() {
    __shared__ int ws[32];
    int tid = threadIdx.x, lane = tid & 31, wid = tid >> 5;
    int i = blockIdx.x * SCAN_BS + tid;
    int v = (i < NN) ? g_cnt[i] : 0;
    int x = v;
    #pragma unroll
    for (int d = 1; d < 32; d <<= 1) {
        int t = __shfl_up_sync(0xffffffffu, x, d);
        if (lane >= d) x += t;
    }
    if (lane == 31) ws[wid] = x;
    __syncthreads();
    if (wid == 0) {
        int y = ws[lane];
        #pragma unroll
        for (int d = 1; d < 32; d <<= 1) {
            int t = __shfl_up_sync(0xffffffffu, y, d);
            if (lane >= d) y += t;
        }
        ws[lane] = y;
    }
    __syncthreads();
    int excl = g_boff[blockIdx.x] + (wid ? ws[wid - 1] : 0) + x - v;
    if (i < NN) {
        g_off[i] = excl;
        g_cur[i] = excl;
        if (i == NN - 1) g_off[NN] = excl + v;
    }
}

__global__ void k_scatter(const int* __restrict__ ei, const float* __restrict__ ew) {
    int e = blockIdx.x * blockDim.x + threadIdx.x;
    if (e < EE) {
        int r = ei[e], c = ei[EE + e];
        float nrm = g_dis[r] * ew[e] * g_dis[c];
        int p = atomicAdd(&g_cur[c], 1);
        g_csc[p] = make_int2(r, __float_as_int(nrm));
    }
}

// ---------------- layer 1: init + pure 2-wide hops ----------------
__global__ void k_init1(const float* __restrict__ c, const int* __restrict__ ip) {
    int n = blockIdx.x * blockDim.x + threadIdx.x;
    if (n >= NN) return;
    int iv = ip[0];
    ((float2*)g_h1)[n] = make_float2((n == iv) ? 1.f : 0.f, c[n]);
}

__global__ void __launch_bounds__(256, 6) k_hop1(int k) {
    int n = blockIdx.x * blockDim.x + threadIdx.x;
    if (n >= NN) return;
    const float2* hc = (const float2*)g_h1 + (size_t)(k - 1) * NN;
    float2* hn = (float2*)g_h1 + (size_t)k * NN;
    int s = g_off[n], e = g_off[n + 1];
    float ax = 0.f, ay = 0.f;
    for (int t = s; t < e; t += 8) {
        #pragma unroll
        for (int j = 0; j < 8; j++) {
            int idx = t + j;
            int2 a = g_csc[idx];
            float w = (idx < e) ? __int_as_float(a.y) : 0.f;
            float2 v = hc[a.x];
            ax = fmaf(w, v.x, ax);
            ay = fmaf(w, v.y, ay);
        }
    }
    hn[n] = make_float2(ax, ay);
}

// ---- combine layer 1: acc1 = b1 + sum_k h1_k W1_k; x2 = relu -> h2 slab 0 --
__global__ void k_comb1(const float* __restrict__ W1, const float* __restrict__ b1) {
    __shared__ float sW[(KHOP + 1) * 30];
    __shared__ float sb[15];
    for (int i = threadIdx.x; i < (KHOP + 1) * 30; i += 256) sW[i] = W1[i];
    if (threadIdx.x < 15) sb[threadIdx.x] = b1[threadIdx.x];
    __syncthreads();
    int n = blockIdx.x * blockDim.x + threadIdx.x;
    if (n >= NN) return;
    float acc[15];
    #pragma unroll
    for (int j = 0; j < 15; j++) acc[j] = sb[j];
    for (int k = 0; k <= KHOP; k++) {
        float2 h = ((const float2*)g_h1)[(size_t)k * NN + n];
        const float* wk = &sW[k * 30];
        #pragma unroll
        for (int j = 0; j < 15; j++) acc[j] = fmaf(h.x, wk[j], fmaf(h.y, wk[15 + j], acc[j]));
    }
    float v[16];
    #pragma unroll
    for (int j = 0; j < 15; j++) v[j] = fmaxf(acc[j], 0.f);
    v[15] = 0.f;
    float4* hp = (float4*)g_h2 + n * 4;   // slab 0
    hp[0] = *(float4*)(v + 0); hp[1] = *(float4*)(v + 4);
    hp[2] = *(float4*)(v + 8); hp[3] = *(float4*)(v + 12);
}

// ---------------- layer 2: pure 16-wide hops (4 lanes/node) ----------------
__global__ void __launch_bounds__(256, 6) k_hop2(int k) {
    int tid = threadIdx.x;
    int g = tid >> 2, l = tid & 3;
    int n = blockIdx.x * 64 + g;
    if (n >= NN) return;
    const float4* hc = (const float4*)(g_h2 + (size_t)(k - 1) * NN * 16);
    float4* hn = (float4*)(g_h2 + (size_t)k * NN * 16);
    int s = g_off[n], e = g_off[n + 1];
    float4 acc = make_float4(0.f, 0.f, 0.f, 0.f);
    for (int t = s; t < e; t += 4) {
        int2 a0 = g_csc[t], a1 = g_csc[t + 1], a2 = g_csc[t + 2], a3 = g_csc[t + 3];
        float w0 = __int_as_float(a0.y);
        float w1 = (t + 1 < e) ? __int_as_float(a1.y) : 0.f;
        float w2 = (t + 2 < e) ? __int_as_float(a2.y) : 0.f;
        float w3 = (t + 3 < e) ? __int_as_float(a3.y) : 0.f;
        float4 v0 = hc[a0.x * 4 + l];
        float4 v1 = hc[a1.x * 4 + l];
        float4 v2 = hc[a2.x * 4 + l];
        float4 v3 = hc[a3.x * 4 + l];
        acc.x = fmaf(w0, v0.x, acc.x); acc.y = fmaf(w0, v0.y, acc.y);
        acc.z = fmaf(w0, v0.z, acc.z); acc.w = fmaf(w0, v0.w, acc.w);
        acc.x = fmaf(w1, v1.x, acc.x); acc.y = fmaf(w1, v1.y, acc.y);
        acc.z = fmaf(w1, v1.z, acc.z); acc.w = fmaf(w1, v1.w, acc.w);
        acc.x = fmaf(w2, v2.x, acc.x); acc.y = fmaf(w2, v2.y, acc.y);
        acc.z = fmaf(w2, v2.z, acc.z); acc.w = fmaf(w2, v2.w, acc.w);
        acc.x = fmaf(w3, v3.x, acc.x); acc.y = fmaf(w3, v3.y, acc.y);
        acc.z = fmaf(w3, v3.z, acc.z); acc.w = fmaf(w3, v3.w, acc.w);
    }
    hn[n * 4 + l] = acc;
}

// ---- combine layer 2: acc2 = b2 + sum_k h2_k W2_k; x3 = relu -> g_x3 -------
__global__ void k_comb2a(const float* __restrict__ W2, const float* __restrict__ b2) {
    __shared__ float sW[17 * 450];
    __shared__ float sb[30];
    int tid = threadIdx.x;
    if (tid < 30) sb[tid] = b2[tid];
    int n = blockIdx.x * 256 + tid;
    float acc[30];
    #pragma unroll
    for (int j = 0; j < 30; j++) acc[j] = 0.f;
    for (int kc = 0; kc < KHOP + 1; kc += 17) {
        __syncthreads();
        for (int i = tid; i < 17 * 450; i += 256) {
            int kk = kc + i / 450;
            if (kk <= KHOP) sW[i] = W2[kk * 450 + i % 450];
        }
        __syncthreads();
        if (n < NN) {
            int kmax = KHOP + 1 - kc; if (kmax > 17) kmax = 17;
            for (int dk = 0; dk < kmax; dk++) {
                int k = kc + dk;
                const float4* hp = (const float4*)(g_h2 + (size_t)k * NN * 16) + n * 4;
                float h[16];
                *(float4*)(h + 0) = hp[0]; *(float4*)(h + 4) = hp[1];
                *(float4*)(h + 8) = hp[2]; *(float4*)(h + 12) = hp[3];
                const float* wk = &sW[dk * 450];
                #pragma unroll
                for (int f = 0; f < 15; f++) {
                    float hf = h[f];
                    #pragma unroll
                    for (int j = 0; j < 30; j++) acc[j] = fmaf(hf, wk[f * 30 + j], acc[j]);
                }
            }
        }
    }
    if (n < NN) {
        float v[32];
        #pragma unroll
        for (int j = 0; j < 30; j++) v[j] = fmaxf(acc[j] + sb[j], 0.f);
        v[30] = 0.f; v[31] = 0.f;
        float4* xp = (float4*)(g_x3 + n * 32);
        #pragma unroll
        for (int q = 0; q < 8; q++) xp[q] = *(float4*)(v + 4 * q);
    }
}

// ---- precompute z3_k = x3 W3_k (b3 folded into k=0) into slabs -------------
__global__ void k_comb2b(const float* __restrict__ W3, const float* __restrict__ b3) {
    __shared__ float sW[17 * 450];
    __shared__ float sb[15];
    int tid = threadIdx.x;
    if (tid < 15) sb[tid] = b3[tid];
    int n = blockIdx.x * 256 + tid;
    float v[30];
    if (n < NN) {
        const float4* xp = (const float4*)(g_x3 + n * 32);
        float tmp[32];
        #pragma unroll
        for (int q = 0; q < 8; q++) *(float4*)(tmp + 4 * q) = xp[q];
        #pragma unroll
        for (int f = 0; f < 30; f++) v[f] = tmp[f];
    }
    for (int kc = 0; kc < KHOP + 1; kc += 17) {
        __syncthreads();
        for (int i = tid; i < 17 * 450; i += 256) {
            int kk = kc + i / 450;
            if (kk <= KHOP) sW[i] = W3[kk * 450 + i % 450];
        }
        __syncthreads();
        if (n < NN) {
            int kmax = KHOP + 1 - kc; if (kmax > 17) kmax = 17;
            for (int dk = 0; dk < kmax; dk++) {
                int k = kc + dk;
                float z[16];
                #pragma unroll
                for (int j = 0; j < 15; j++) z[j] = (k == 0) ? sb[j] : 0.f;
                z[15] = 0.f;
                const float* wk = &sW[dk * 450];
                #pragma unroll
                for (int f = 0; f < 30; f++) {
                    float vf = v[f];
                    #pragma unroll
                    for (int j = 0; j < 15; j++) z[j] = fmaf(vf, wk[f * 15 + j], z[j]);
                }
                float4* zp = (float4*)(g_z3 + (size_t)k * NN * 16) + n * 4;
                zp[0] = *(float4*)(z + 0); zp[1] = *(float4*)(z + 4);
                zp[2] = *(float4*)(z + 8); zp[3] = *(float4*)(z + 12);
            }
        }
    }
}

// ------- layer 3 Horner hop (pure): t_new = A t_old + z3_k ------------------
// first: t_old = z3 slab KHOP; wsel: 1 -> write g_ha (read g_hb), 0 -> write g_hb
__global__ void __launch_bounds__(256, 6) k_hop3(int first, int wsel, int k) {
    int tid = threadIdx.x;
    int g = tid >> 2, l = tid & 3;
    int n = blockIdx.x * 64 + g;
    if (n >= NN) return;
    const float4* t_old = first ? ((const float4*)(g_z3 + (size_t)KHOP * NN * 16))
                                : (wsel ? (const float4*)g_hb : (const float4*)g_ha);
    float4* t_new = wsel ? (float4*)g_ha : (float4*)g_hb;
    int s = g_off[n], e = g_off[n + 1];
    float4 acc = make_float4(0.f, 0.f, 0.f, 0.f);
    for (int t = s; t < e; t += 4) {
        int2 a0 = g_csc[t], a1 = g_csc[t + 1], a2 = g_csc[t + 2], a3 = g_csc[t + 3];
        float w0 = __int_as_float(a0.y);
        float w1 = (t + 1 < e) ? __int_as_float(a1.y) : 0.f;
        float w2 = (t + 2 < e) ? __int_as_float(a2.y) : 0.f;
        float w3 = (t + 3 < e) ? __int_as_float(a3.y) : 0.f;
        float4 v0 = t_old[a0.x * 4 + l];
        float4 v1 = t_old[a1.x * 4 + l];
        float4 v2 = t_old[a2.x * 4 + l];
        float4 v3 = t_old[a3.x * 4 + l];
        acc.x = fmaf(w0, v0.x, acc.x); acc.y = fmaf(w0, v0.y, acc.y);
        acc.z = fmaf(w0, v0.z, acc.z); acc.w = fmaf(w0, v0.w, acc.w);
        acc.x = fmaf(w1, v1.x, acc.x); acc.y = fmaf(w1, v1.y, acc.y);
        acc.z = fmaf(w1, v1.z, acc.z); acc.w = fmaf(w1, v1.w, acc.w);
        acc.x = fmaf(w2, v2.x, acc.x); acc.y = fmaf(w2, v2.y, acc.y);
        acc.z = fmaf(w2, v2.z, acc.z); acc.w = fmaf(w2, v2.w, acc.w);
        acc.x = fmaf(w3, v3.x, acc.x); acc.y = fmaf(w3, v3.y, acc.y);
        acc.z = fmaf(w3, v3.z, acc.z); acc.w = fmaf(w3, v3.w, acc.w);
    }
    float4 z = ((const float4*)(g_z3 + (size_t)k * NN * 16))[n * 4 + l];
    acc.x += z.x; acc.y += z.y; acc.z += z.z; acc.w += z.w;
    t_new[n * 4 + l] = acc;
}

// ---- transition 3->4: x4 = relu(t3 in g_hb); z4[k][n] = x4 . W4_k ---------
__global__ void k_z4(const float* __restrict__ W4, const float* __restrict__ b4) {
    __shared__ float sW[(KHOP + 1) * 15];
    __shared__ float sb0;
    for (int idx = threadIdx.x; idx < (KHOP + 1) * 15; idx += 256) sW[idx] = W4[idx];
    if (threadIdx.x == 0) sb0 = b4[0];
    __syncthreads();
    int n = blockIdx.x * blockDim.x + threadIdx.x;
    if (n >= NN) return;
    float v[16];
    const float4* tp = (const float4*)(g_hb + n * 16);  // 50 hops -> final t3 in g_hb
    *(float4*)(v + 0) = tp[0]; *(float4*)(v + 4) = tp[1];
    *(float4*)(v + 8) = tp[2]; *(float4*)(v + 12) = tp[3];
    #pragma unroll
    for (int f = 0; f < 15; f++) v[f] = fmaxf(v[f], 0.f);
    for (int k = 0; k <= KHOP; k++) {
        float z = (k == 0) ? sb0 : 0.f;
        #pragma unroll
        for (int f = 0; f < 15; f++) z = fmaf(v[f], sW[k * 15 + f], z);
        g_z4[(size_t)k * NN + n] = z;
    }
}

// ------------- layer 4 Horner hop (width 1, 1 thread/node) ------------------
// mode: 0 -> told = g_z4[KHOP], 1 -> told = g_t4a, 2 -> told = g_t4b
__global__ void __launch_bounds__(256, 6) k_hop4(int mode, int wout, int kidx,
                                                 int fin, float* __restrict__ out) {
    int n = blockIdx.x * blockDim.x + threadIdx.x;
    if (n >= NN) return;
    const float* told = (mode == 0) ? (g_z4 + (size_t)KHOP * NN)
                                    : (mode == 1 ? g_t4a : g_t4b);
    float* tnew = wout ? g_t4b : g_t4a;
    int s = g_off[n], e = g_off[n + 1];
    float sum = 0.f;
    for (int t = s; t < e; t += 8) {
        #pragma unroll
        for (int j = 0; j < 8; j++) {
            int idx = t + j;
            int2 a = g_csc[idx];
            float w = (idx < e) ? __int_as_float(a.y) : 0.f;
            sum = fmaf(w, __ldg(told + a.x), sum);
        }
    }
    float r = g_z4[(size_t)kidx * NN + n] + sum;
    if (fin) out[n] = fmaxf(r, 0.f);
    else tnew[n] = r;
}

// ---------------- host launch ----------------
static inline int div_up(int a, int b) { return (a + b - 1) / b; }

extern "C" void kernel_launch(void* const* d_in, const int* in_sizes, int n_in,
                              void* d_out, int out_size) {
    const int*   ei = (const int*)d_in[0];
    const float* ew = (const float*)d_in[1];
    const float* c  = (const float*)d_in[2];
    const int*   ip = (const int*)d_in[3];
    const float* W1 = (const float*)d_in[4];
    const float* b1 = (const float*)d_in[5];
    const float* W2 = (const float*)d_in[6];
    const float* b2 = (const float*)d_in[7];
    const float* W3 = (const float*)d_in[8];
    const float* b3 = (const float*)d_in[9];
    const float* W4 = (const float*)d_in[10];
    const float* b4 = (const float*)d_in[11];
    float* out = (float*)d_out;

    int nb = div_up(NN, 256);
    int eb = div_up(EE, 256);
    int hb = div_up(NN, 64);   // 4 lanes/node hop kernels

    // graph preprocessing
    k_zero<<<nb, 256>>>();
    k_degcnt<<<eb, 256>>>(ei, ew);
    k_dis<<<nb, 256>>>();
    k_bsum<<<NBLK_SCAN, SCAN_BS>>>();
    k_bscan<<<1, 128>>>();
    k_scan2<<<NBLK_SCAN, SCAN_BS>>>();
    k_scatter<<<eb, 256>>>(ei, ew);

    // layer 1: pure hops into slabs, then combine
    k_init1<<<nb, 256>>>(c, ip);
    for (int k = 1; k <= KHOP; k++) k_hop1<<<nb, 256>>>(k);
    k_comb1<<<nb, 256>>>(W1, b1);

    // layer 2: pure hops into slabs, then combine -> x3
    for (int k = 1; k <= KHOP; k++) k_hop2<<<hb, 256>>>(k);
    k_comb2a<<<nb, 256>>>(W2, b2);

    // layer 3: z3 precompute, then pure Horner hops
    k_comb2b<<<nb, 256>>>(W3, b3);
    for (int idx = 0; idx < KHOP; idx++) {
        int k = KHOP - 1 - idx;
        k_hop3<<<hb, 256>>>((idx == 0) ? 1 : 0, ((idx & 1) == 0) ? 1 : 0, k);
    }
    // idx even writes g_ha, idx odd writes g_hb; idx=49 (odd) -> final in g_hb

    // layer 4: Horner width 1 with precomputed z; final hop writes out
    k_z4<<<nb, 256>>>(W4, b4);
    int mode = 0, w = 0;
    for (int k = KHOP - 1; k >= 0; k--) {
        k_hop4<<<nb, 256>>>(mode, w, k, (k == 0) ? 1 : 0, out);
        mode = w ? 2 : 1;
        w ^= 1;
    }
}